// round 1
// baseline (speedup 1.0000x reference)
#include <cuda_runtime.h>
#include <math.h>

#define B_   2
#define T_   2048
#define C_   1024
#define H_   16
#define D_   64
#define NTOK (B_*T_)
#define DFF  4096

// ---------------- scratch (no allocation allowed) ----------------
__device__ float g_h  [NTOK*C_];
__device__ float g_q  [NTOK*C_];
__device__ float g_k  [NTOK*C_];
__device__ float g_v  [NTOK*C_];
__device__ float g_att[NTOK*C_];
__device__ float g_x1 [NTOK*C_];
__device__ float g_h2 [NTOK*C_];
__device__ float g_f1 [NTOK*DFF];

// ---------------- LayerNorm: one block per row ----------------
__global__ void __launch_bounds__(256) ln_kernel(const float* __restrict__ x,
                                                 const float* __restrict__ w,
                                                 const float* __restrict__ b,
                                                 float* __restrict__ y)
{
    __shared__ float red[32];
    int row = blockIdx.x;
    int tid = threadIdx.x;
    const float* xr = x + (size_t)row * C_;
    float v[4];
#pragma unroll
    for (int k = 0; k < 4; k++) v[k] = xr[tid + 256*k];

    float s = v[0] + v[1] + v[2] + v[3];
#pragma unroll
    for (int o = 16; o > 0; o >>= 1) s += __shfl_xor_sync(~0u, s, o);
    if ((tid & 31) == 0) red[tid >> 5] = s;
    __syncthreads();
    if (tid < 32) {
        float t = (tid < 8) ? red[tid] : 0.f;
#pragma unroll
        for (int o = 4; o > 0; o >>= 1) t += __shfl_xor_sync(~0u, t, o);
        if (tid == 0) red[0] = t;
    }
    __syncthreads();
    float mu = red[0] * (1.0f / C_);
    __syncthreads();

    float sq = 0.f;
#pragma unroll
    for (int k = 0; k < 4; k++) { float d = v[k] - mu; sq += d * d; }
#pragma unroll
    for (int o = 16; o > 0; o >>= 1) sq += __shfl_xor_sync(~0u, sq, o);
    if ((tid & 31) == 0) red[tid >> 5] = sq;
    __syncthreads();
    if (tid < 32) {
        float t = (tid < 8) ? red[tid] : 0.f;
#pragma unroll
        for (int o = 4; o > 0; o >>= 1) t += __shfl_xor_sync(~0u, t, o);
        if (tid == 0) red[0] = t;
    }
    __syncthreads();
    float var = red[0] * (1.0f / C_);
    float rs = rsqrtf(var + 1e-5f);
    float* yr = y + (size_t)row * C_;
#pragma unroll
    for (int k = 0; k < 4; k++) {
        int c = tid + 256*k;
        yr[c] = (v[k] - mu) * rs * w[c] + b[c];
    }
}

// ---------------- SGEMM 128x128x8, 8x8 register tiles ----------------
// MODE 0: C = acc + bias
// MODE 1: C = resid + gamma * (acc + bias)
// MODE 2: C = gelu_exact(acc + bias)
template<int MODE>
__global__ void __launch_bounds__(256) sgemm_kernel(
    const float* __restrict__ A, const float* __restrict__ Bw,
    const float* __restrict__ bias,
    const float* __restrict__ resid, const float* __restrict__ gamma,
    float* __restrict__ Cout, int M, int N, int K)
{
    __shared__ float As[8][128];   // transposed A tile
    __shared__ float Bs[8][128];
    int tid = threadIdx.x;
    int tx = tid & 15, ty = tid >> 4;
    int m0 = blockIdx.y << 7, n0 = blockIdx.x << 7;

    float acc[8][8];
#pragma unroll
    for (int i = 0; i < 8; i++)
#pragma unroll
        for (int j = 0; j < 8; j++) acc[i][j] = 0.f;

    int arow = tid >> 1;
    int acol = (tid & 1) << 2;
    int brow = tid >> 5;
    int bcol = (tid & 31) << 2;
    const float* Ap = A  + (size_t)(m0 + arow) * K + acol;
    const float* Bp = Bw + (size_t)brow * N + n0 + bcol;

    for (int k0 = 0; k0 < K; k0 += 8) {
        float4 av = *(const float4*)(Ap + k0);
        float4 bv = *(const float4*)(Bp + (size_t)k0 * N);
        As[acol + 0][arow] = av.x;
        As[acol + 1][arow] = av.y;
        As[acol + 2][arow] = av.z;
        As[acol + 3][arow] = av.w;
        *(float4*)&Bs[brow][bcol] = bv;
        __syncthreads();
#pragma unroll
        for (int kk = 0; kk < 8; kk++) {
            float a[8], bb[8];
            *(float4*)&a[0]  = *(const float4*)&As[kk][(ty << 3)];
            *(float4*)&a[4]  = *(const float4*)&As[kk][(ty << 3) + 4];
            *(float4*)&bb[0] = *(const float4*)&Bs[kk][(tx << 3)];
            *(float4*)&bb[4] = *(const float4*)&Bs[kk][(tx << 3) + 4];
#pragma unroll
            for (int i = 0; i < 8; i++)
#pragma unroll
                for (int j = 0; j < 8; j++)
                    acc[i][j] = fmaf(a[i], bb[j], acc[i][j]);
        }
        __syncthreads();
    }

#pragma unroll
    for (int i = 0; i < 8; i++) {
        int row = m0 + (ty << 3) + i;
        size_t base = (size_t)row * N + n0 + (tx << 3);
#pragma unroll
        for (int j = 0; j < 8; j++) {
            int col = n0 + (tx << 3) + j;
            float val = acc[i][j] + bias[col];
            if (MODE == 1)      val = resid[base + j] + gamma[col] * val;
            else if (MODE == 2) val = 0.5f * val * (1.0f + erff(val * 0.70710678118654752f));
            Cout[base + j] = val;
        }
    }
}

// ---------------- Flash attention (fp32, online softmax) ----------------
// Q,K,V in [B,T,H*D] layout. One block = 32 queries x one head.
#define ATTN_SMEM_FLOATS (32*64 + 64*65 + 64*65 + 32*65 + 96)
#define ATTN_SMEM_BYTES  (ATTN_SMEM_FLOATS * 4)

__global__ void __launch_bounds__(128) attn_kernel(
    const float* __restrict__ Q, const float* __restrict__ Kx,
    const float* __restrict__ Vx, const int* __restrict__ mask,
    float* __restrict__ Out)
{
    extern __shared__ float sm[];
    float* sQ = sm;                // [32][64]
    float* sK = sQ + 32*64;        // [64][65]
    float* sV = sK + 64*65;        // [64][65]
    float* sP = sV + 64*65;        // [32][65]
    float* sM = sP + 32*65;        // [32]
    float* sL = sM + 32;           // [32]
    float* sF = sL + 32;           // [32]

    int tid = threadIdx.x;
    int tx = tid & 15, ty = tid >> 4;     // tx: 0..15 (key/dim cols), ty: 0..7 (query rows)
    int b = blockIdx.z, h = blockIdx.y;
    int q0 = blockIdx.x << 5;

    // load Q tile [32 x 64]
    for (int e = tid; e < 32 * 16; e += 128) {
        int row = e >> 4, c4 = (e & 15) << 2;
        float4 qv = *(const float4*)(Q + ((size_t)(b * T_ + q0 + row) * C_) + h * D_ + c4);
        *(float4*)&sQ[row * 64 + c4] = qv;
    }
    if (tid < 32) { sM[tid] = -1e30f; sL[tid] = 0.f; }

    float o[4][4];
#pragma unroll
    for (int i = 0; i < 4; i++)
#pragma unroll
        for (int j = 0; j < 4; j++) o[i][j] = 0.f;

    const float scale = 0.125f;   // 1/sqrt(64)

    for (int k0 = 0; k0 < T_; k0 += 64) {
        __syncthreads();   // protect smem from previous iteration / init
        // load K,V tiles [64 x 64] (padded stride 65)
        for (int e = tid; e < 64 * 16; e += 128) {
            int row = e >> 4, c4 = (e & 15) << 2;
            size_t gof = ((size_t)(b * T_ + k0 + row) * C_) + h * D_ + c4;
            float4 kv = *(const float4*)(Kx + gof);
            sK[row * 65 + c4 + 0] = kv.x;
            sK[row * 65 + c4 + 1] = kv.y;
            sK[row * 65 + c4 + 2] = kv.z;
            sK[row * 65 + c4 + 3] = kv.w;
            float4 vv = *(const float4*)(Vx + gof);
            sV[row * 65 + c4 + 0] = vv.x;
            sV[row * 65 + c4 + 1] = vv.y;
            sV[row * 65 + c4 + 2] = vv.z;
            sV[row * 65 + c4 + 3] = vv.w;
        }
        __syncthreads();

        // S = Q K^T  (4x4 per thread)
        float s[4][4];
#pragma unroll
        for (int i = 0; i < 4; i++)
#pragma unroll
            for (int j = 0; j < 4; j++) s[i][j] = 0.f;
#pragma unroll 4
        for (int d = 0; d < 64; d++) {
            float qv[4], kv[4];
#pragma unroll
            for (int i = 0; i < 4; i++) qv[i] = sQ[(4 * ty + i) * 64 + d];
#pragma unroll
            for (int j = 0; j < 4; j++) kv[j] = sK[(4 * tx + j) * 65 + d];
#pragma unroll
            for (int i = 0; i < 4; i++)
#pragma unroll
                for (int j = 0; j < 4; j++) s[i][j] = fmaf(qv[i], kv[j], s[i][j]);
        }
        // mask + scale -> sP
        bool mok[4];
#pragma unroll
        for (int j = 0; j < 4; j++) mok[j] = mask[b * T_ + k0 + 4 * tx + j] != 0;
#pragma unroll
        for (int i = 0; i < 4; i++)
#pragma unroll
            for (int j = 0; j < 4; j++)
                sP[(4 * ty + i) * 65 + 4 * tx + j] = mok[j] ? s[i][j] * scale : -1e30f;
        __syncthreads();

        // online softmax stats: 4 threads per row
        {
            int r = tid >> 2, sub = tid & 3;
            float mloc = -1e30f;
#pragma unroll
            for (int k = 0; k < 16; k++) mloc = fmaxf(mloc, sP[r * 65 + sub * 16 + k]);
            mloc = fmaxf(mloc, __shfl_xor_sync(~0u, mloc, 1));
            mloc = fmaxf(mloc, __shfl_xor_sync(~0u, mloc, 2));
            float mold = sM[r];
            float mnew = fmaxf(mold, mloc);
            float ssum = 0.f;
#pragma unroll
            for (int k = 0; k < 16; k++) {
                int idx = r * 65 + sub * 16 + k;
                float p = __expf(sP[idx] - mnew);
                sP[idx] = p;
                ssum += p;
            }
            ssum += __shfl_xor_sync(~0u, ssum, 1);
            ssum += __shfl_xor_sync(~0u, ssum, 2);
            if (sub == 0) {
                sF[r] = __expf(mold - mnew);
                sL[r] = sL[r] * sF[r] + ssum;
                sM[r] = mnew;
            }
        }
        __syncthreads();

        // rescale O and accumulate O += P V
        float fr[4];
#pragma unroll
        for (int i = 0; i < 4; i++) fr[i] = sF[4 * ty + i];
#pragma unroll
        for (int i = 0; i < 4; i++)
#pragma unroll
            for (int j = 0; j < 4; j++) o[i][j] *= fr[i];
#pragma unroll 4
        for (int c = 0; c < 64; c++) {
            float pv[4], vv[4];
#pragma unroll
            for (int i = 0; i < 4; i++) pv[i] = sP[(4 * ty + i) * 65 + c];
#pragma unroll
            for (int j = 0; j < 4; j++) vv[j] = sV[c * 65 + 4 * tx + j];
#pragma unroll
            for (int i = 0; i < 4; i++)
#pragma unroll
                for (int j = 0; j < 4; j++) o[i][j] = fmaf(pv[i], vv[j], o[i][j]);
        }
    }

    // write normalized output
#pragma unroll
    for (int i = 0; i < 4; i++) {
        int row = q0 + 4 * ty + i;
        float inv = 1.0f / sL[4 * ty + i];
        float4 ov;
        ov.x = o[i][0] * inv; ov.y = o[i][1] * inv;
        ov.z = o[i][2] * inv; ov.w = o[i][3] * inv;
        *(float4*)(Out + ((size_t)(b * T_ + row) * C_) + h * D_ + 4 * tx) = ov;
    }
}

// ---------------- host launcher ----------------
extern "C" void kernel_launch(void* const* d_in, const int* in_sizes, int n_in,
                              void* d_out, int out_size)
{
    const float* x    = (const float*)d_in[0];
    const int*   mask = (const int*)  d_in[1];
    const float* ln1w = (const float*)d_in[2];
    const float* ln1b = (const float*)d_in[3];
    const float* ln2w = (const float*)d_in[4];
    const float* ln2b = (const float*)d_in[5];
    const float* qw   = (const float*)d_in[6];
    const float* qb   = (const float*)d_in[7];
    const float* kw   = (const float*)d_in[8];
    const float* kb   = (const float*)d_in[9];
    const float* vw   = (const float*)d_in[10];
    const float* vb   = (const float*)d_in[11];
    const float* ow   = (const float*)d_in[12];
    const float* ob   = (const float*)d_in[13];
    const float* f1w  = (const float*)d_in[14];
    const float* f1b  = (const float*)d_in[15];
    const float* f2w  = (const float*)d_in[16];
    const float* f2b  = (const float*)d_in[17];
    const float* gm1  = (const float*)d_in[18];
    const float* gm2  = (const float*)d_in[19];
    float* out = (float*)d_out;

    float *ph, *pq, *pk, *pv, *pa, *px1, *ph2, *pf1;
    cudaGetSymbolAddress((void**)&ph,  g_h);
    cudaGetSymbolAddress((void**)&pq,  g_q);
    cudaGetSymbolAddress((void**)&pk,  g_k);
    cudaGetSymbolAddress((void**)&pv,  g_v);
    cudaGetSymbolAddress((void**)&pa,  g_att);
    cudaGetSymbolAddress((void**)&px1, g_x1);
    cudaGetSymbolAddress((void**)&ph2, g_h2);
    cudaGetSymbolAddress((void**)&pf1, g_f1);

    cudaFuncSetAttribute(attn_kernel,
                         cudaFuncAttributeMaxDynamicSharedMemorySize,
                         ATTN_SMEM_BYTES);

    dim3 gridC(C_ / 128, NTOK / 128);   // N=1024 GEMMs
    dim3 gridF(DFF / 128, NTOK / 128);  // N=4096 GEMM

    // 1) LN1
    ln_kernel<<<NTOK, 256>>>(x, ln1w, ln1b, ph);
    // 2) Q,K,V projections
    sgemm_kernel<0><<<gridC, 256>>>(ph, qw, qb, nullptr, nullptr, pq, NTOK, C_, C_);
    sgemm_kernel<0><<<gridC, 256>>>(ph, kw, kb, nullptr, nullptr, pk, NTOK, C_, C_);
    sgemm_kernel<0><<<gridC, 256>>>(ph, vw, vb, nullptr, nullptr, pv, NTOK, C_, C_);
    // 3) attention
    attn_kernel<<<dim3(T_ / 32, H_, B_), 128, ATTN_SMEM_BYTES>>>(pq, pk, pv, mask, pa);
    // 4) O projection + residual (x + gamma1 * (...))
    sgemm_kernel<1><<<gridC, 256>>>(pa, ow, ob, x, gm1, px1, NTOK, C_, C_);
    // 5) LN2
    ln_kernel<<<NTOK, 256>>>(px1, ln2w, ln2b, ph2);
    // 6) FFN up + exact GELU
    sgemm_kernel<2><<<gridF, 256>>>(ph2, f1w, f1b, nullptr, nullptr, pf1, NTOK, DFF, C_);
    // 7) FFN down + residual -> out
    sgemm_kernel<1><<<gridC, 256>>>(pf1, f2w, f2b, px1, gm2, out, NTOK, C_, DFF);
}

// round 3
// speedup vs baseline: 1.9097x; 1.9097x over previous
#include <cuda_runtime.h>
#include <cuda_bf16.h>
#include <cstdint>
#include <stdint.h>
#include <math.h>

typedef unsigned int u32;

#define B_   2
#define T_   2048
#define C_   1024
#define H_   16
#define D_   64
#define NTOK (B_*T_)
#define DFF  4096

// ---------------- scratch (no allocation allowed) ----------------
__device__ float g_h  [NTOK*C_];
__device__ float g_q  [NTOK*C_];
__device__ float g_k  [NTOK*C_];
__device__ float g_v  [NTOK*C_];
__device__ float g_att[NTOK*C_];
__device__ float g_x1 [NTOK*C_];
__device__ float g_h2 [NTOK*C_];
__device__ float g_f1 [NTOK*DFF];

// ---------------- LayerNorm: one block per row ----------------
__global__ void __launch_bounds__(256) ln_kernel(const float* __restrict__ x,
                                                 const float* __restrict__ w,
                                                 const float* __restrict__ b,
                                                 float* __restrict__ y)
{
    __shared__ float red[32];
    int row = blockIdx.x;
    int tid = threadIdx.x;
    const float* xr = x + (size_t)row * C_;
    float v[4];
#pragma unroll
    for (int k = 0; k < 4; k++) v[k] = xr[tid + 256*k];

    float s = v[0] + v[1] + v[2] + v[3];
#pragma unroll
    for (int o = 16; o > 0; o >>= 1) s += __shfl_xor_sync(~0u, s, o);
    if ((tid & 31) == 0) red[tid >> 5] = s;
    __syncthreads();
    if (tid < 32) {
        float t = (tid < 8) ? red[tid] : 0.f;
#pragma unroll
        for (int o = 4; o > 0; o >>= 1) t += __shfl_xor_sync(~0u, t, o);
        if (tid == 0) red[0] = t;
    }
    __syncthreads();
    float mu = red[0] * (1.0f / C_);
    __syncthreads();

    float sq = 0.f;
#pragma unroll
    for (int k = 0; k < 4; k++) { float d = v[k] - mu; sq += d * d; }
#pragma unroll
    for (int o = 16; o > 0; o >>= 1) sq += __shfl_xor_sync(~0u, sq, o);
    if ((tid & 31) == 0) red[tid >> 5] = sq;
    __syncthreads();
    if (tid < 32) {
        float t = (tid < 8) ? red[tid] : 0.f;
#pragma unroll
        for (int o = 4; o > 0; o >>= 1) t += __shfl_xor_sync(~0u, t, o);
        if (tid == 0) red[0] = t;
    }
    __syncthreads();
    float var = red[0] * (1.0f / C_);
    float rs = rsqrtf(var + 1e-5f);
    float* yr = y + (size_t)row * C_;
#pragma unroll
    for (int k = 0; k < 4; k++) {
        int c = tid + 256*k;
        yr[c] = (v[k] - mu) * rs * w[c] + b[c];
    }
}

// ---------------- bf16 tensor-core GEMM helpers ----------------
__device__ __forceinline__ u32 pack_bf16(float x, float y) {
    __nv_bfloat162 t = __floats2bfloat162_rn(x, y);
    u32 r;
    memcpy(&r, &t, 4);
    return r;
}

__device__ __forceinline__ void ldsm_x4(u32& r0, u32& r1,
                                        u32& r2, u32& r3, u32 addr) {
    asm volatile("ldmatrix.sync.aligned.m8n8.x4.shared.b16 {%0,%1,%2,%3},[%4];"
                 : "=r"(r0), "=r"(r1), "=r"(r2), "=r"(r3) : "r"(addr));
}
__device__ __forceinline__ void ldsm_x4_t(u32& r0, u32& r1,
                                          u32& r2, u32& r3, u32 addr) {
    asm volatile("ldmatrix.sync.aligned.m8n8.x4.trans.shared.b16 {%0,%1,%2,%3},[%4];"
                 : "=r"(r0), "=r"(r1), "=r"(r2), "=r"(r3) : "r"(addr));
}
__device__ __forceinline__ void mma_bf16(float* c, const u32* a, u32 b0, u32 b1) {
    asm volatile("mma.sync.aligned.m16n8k16.row.col.f32.bf16.bf16.f32 "
                 "{%0,%1,%2,%3},{%4,%5,%6,%7},{%8,%9},{%0,%1,%2,%3};"
                 : "+f"(c[0]), "+f"(c[1]), "+f"(c[2]), "+f"(c[3])
                 : "r"(a[0]), "r"(a[1]), "r"(a[2]), "r"(a[3]), "r"(b0), "r"(b1));
}

// ---------------- GEMM 128x128x32, bf16 MMA, fp32 accum ----------------
// MODE 0: C = acc + bias
// MODE 1: C = resid + gamma * (acc + bias)
// MODE 2: C = gelu_exact(acc + bias)
#define SA_STRIDE 20
#define SB_STRIDE 68
#define SA_U32   (128*SA_STRIDE)
#define SB_U32   (32*SB_STRIDE)
#define SA_BYTES (SA_U32*4)
#define SB_BYTES (SB_U32*4)

template<int MODE>
__global__ void __launch_bounds__(256) bgemm_kernel(
    const float* __restrict__ A, const float* __restrict__ Bw,
    const float* __restrict__ bias,
    const float* __restrict__ resid, const float* __restrict__ gamma,
    float* __restrict__ Cout, int M, int N, int K)
{
    __shared__ u32 sA[2][SA_U32];
    __shared__ u32 sB[2][SB_U32];

    const int tid  = threadIdx.x;
    const int lane = tid & 31, warp = tid >> 5;
    const int warp_m = warp >> 2, warp_n = warp & 3;   // 2 x 4 warp grid
    const int m_blk = blockIdx.y << 7, n_blk = blockIdx.x << 7;

    // global load assignments
    const int arow = tid >> 1;             // 0..127
    const int acol = (tid & 1) << 4;       // 0 / 16
    const int brow = tid >> 3;             // 0..31
    const int bcol = (tid & 7) << 4;       // 0..112
    const float* Ag = A  + (size_t)(m_blk + arow) * K + acol;
    const float* Bg = Bw + (size_t)brow * N + n_blk + bcol;

    // smem store pointers
    u32* sAp = &sA[0][arow * SA_STRIDE + (acol >> 1)];
    u32* sBp = &sB[0][brow * SB_STRIDE + (bcol >> 1)];

    // ldmatrix base addresses
    const int g  = lane >> 3;     // 0..3
    const int r8 = lane & 7;
    u32 sA_base = (u32)__cvta_generic_to_shared(&sA[0][0]);
    u32 sB_base = (u32)__cvta_generic_to_shared(&sB[0][0]);
    // A fragment: lanes 0-7 rows 0-7 col0 | 8-15 rows 8-15 col0 | 16-23 rows 0-7 col8 | 24-31 rows 8-15 col8
    u32 aAddr0 = sA_base + (u32)(warp_m*64 + r8 + (g&1)*8) * (SA_STRIDE*4)
                         + (u32)((g>>1)*8) * 2;
    // B fragment (trans): k-rows x n-cols
    u32 bAddr0 = sB_base + (u32)(r8 + (g&1)*8) * (SB_STRIDE*4)
                         + (u32)(warp_n*32 + (g>>1)*8) * 2;

    float acc[4][4][4];
#pragma unroll
    for (int mt = 0; mt < 4; mt++)
#pragma unroll
        for (int nt = 0; nt < 4; nt++)
#pragma unroll
            for (int i = 0; i < 4; i++) acc[mt][nt][i] = 0.f;

    // ---- prologue: stage tile 0 into smem buffer 0 ----
    u32 sax[4], say[4], sbx[4], sby[4];
#pragma unroll
    for (int i = 0; i < 4; i++) {
        float4 t = *(const float4*)(Ag + i*4);
        sax[i] = pack_bf16(t.x, t.y); say[i] = pack_bf16(t.z, t.w);
        float4 uvec = *(const float4*)(Bg + i*4);
        sbx[i] = pack_bf16(uvec.x, uvec.y); sby[i] = pack_bf16(uvec.z, uvec.w);
    }
#pragma unroll
    for (int i = 0; i < 4; i++) {
        sAp[i*2] = sax[i]; sAp[i*2+1] = say[i];
        sBp[i*2] = sbx[i]; sBp[i*2+1] = sby[i];
    }
    __syncthreads();

    const int nk = K >> 5;
    for (int kt = 0; kt < nk; kt++) {
        const int cur = kt & 1;
        if (kt + 1 < nk) {
            const float* Agn = Ag + ((kt+1) << 5);
            const float* Bgn = Bg + (size_t)((kt+1) << 5) * N;
#pragma unroll
            for (int i = 0; i < 4; i++) {
                float4 t = *(const float4*)(Agn + i*4);
                sax[i] = pack_bf16(t.x, t.y); say[i] = pack_bf16(t.z, t.w);
                float4 uvec = *(const float4*)(Bgn + i*4);
                sbx[i] = pack_bf16(uvec.x, uvec.y); sby[i] = pack_bf16(uvec.z, uvec.w);
            }
        }

        const u32 aB = aAddr0 + cur * SA_BYTES;
        const u32 bB = bAddr0 + cur * SB_BYTES;
#pragma unroll
        for (int ks = 0; ks < 2; ks++) {
            u32 af[4][4];
#pragma unroll
            for (int mt = 0; mt < 4; mt++)
                ldsm_x4(af[mt][0], af[mt][1], af[mt][2], af[mt][3],
                        aB + (u32)(mt*16) * (SA_STRIDE*4) + (u32)(ks*16)*2);
            u32 bf0[4], bf1[4];
            ldsm_x4_t(bf0[0], bf0[1], bf0[2], bf0[3],
                      bB + (u32)(ks*16) * (SB_STRIDE*4));
            ldsm_x4_t(bf1[0], bf1[1], bf1[2], bf1[3],
                      bB + (u32)(ks*16) * (SB_STRIDE*4) + 32);
#pragma unroll
            for (int mt = 0; mt < 4; mt++) {
                mma_bf16(acc[mt][0], af[mt], bf0[0], bf0[1]);
                mma_bf16(acc[mt][1], af[mt], bf0[2], bf0[3]);
                mma_bf16(acc[mt][2], af[mt], bf1[0], bf1[1]);
                mma_bf16(acc[mt][3], af[mt], bf1[2], bf1[3]);
            }
        }

        if (kt + 1 < nk) {
            const int nxt = cur ^ 1;
            u32* dAp = sAp + nxt * SA_U32;
            u32* dBp = sBp + nxt * SB_U32;
#pragma unroll
            for (int i = 0; i < 4; i++) {
                dAp[i*2] = sax[i]; dAp[i*2+1] = say[i];
                dBp[i*2] = sbx[i]; dBp[i*2+1] = sby[i];
            }
        }
        __syncthreads();
    }

    // ---- epilogue ----
    const int rr = lane >> 2, cc = (lane & 3) << 1;
    const int row0 = m_blk + warp_m * 64;
    const int col0 = n_blk + warp_n * 32;
#pragma unroll
    for (int mt = 0; mt < 4; mt++) {
#pragma unroll
        for (int nt = 0; nt < 4; nt++) {
            const int col = col0 + nt * 8 + cc;
            float2 b2 = *(const float2*)(bias + col);
            float2 g2 = make_float2(0.f, 0.f);
            if (MODE == 1) g2 = *(const float2*)(gamma + col);
#pragma unroll
            for (int half = 0; half < 2; half++) {
                const int row = row0 + mt * 16 + rr + half * 8;
                const size_t off = (size_t)row * N + col;
                float v0 = acc[mt][nt][half*2 + 0] + b2.x;
                float v1 = acc[mt][nt][half*2 + 1] + b2.y;
                if (MODE == 1) {
                    float2 rv = *(const float2*)(resid + off);
                    v0 = rv.x + g2.x * v0;
                    v1 = rv.y + g2.y * v1;
                } else if (MODE == 2) {
                    v0 = 0.5f * v0 * (1.0f + erff(v0 * 0.70710678118654752f));
                    v1 = 0.5f * v1 * (1.0f + erff(v1 * 0.70710678118654752f));
                }
                float2 ov; ov.x = v0; ov.y = v1;
                *(float2*)(Cout + off) = ov;
            }
        }
    }
}

// ---------------- Flash attention (fp32, online softmax) ----------------
#define ATTN_SMEM_FLOATS (32*64 + 64*65 + 64*65 + 32*65 + 96)
#define ATTN_SMEM_BYTES  (ATTN_SMEM_FLOATS * 4)

__global__ void __launch_bounds__(128) attn_kernel(
    const float* __restrict__ Q, const float* __restrict__ Kx,
    const float* __restrict__ Vx, const int* __restrict__ mask,
    float* __restrict__ Out)
{
    extern __shared__ float smbuf[];
    float* sQ = smbuf;             // [32][64]
    float* sK = sQ + 32*64;        // [64][65]
    float* sV = sK + 64*65;        // [64][65]
    float* sP = sV + 64*65;        // [32][65]
    float* sM = sP + 32*65;
    float* sL = sM + 32;
    float* sF = sL + 32;

    int tid = threadIdx.x;
    int tx = tid & 15, ty = tid >> 4;
    int b = blockIdx.z, h = blockIdx.y;
    int q0 = blockIdx.x << 5;

    for (int e = tid; e < 32 * 16; e += 128) {
        int row = e >> 4, c4 = (e & 15) << 2;
        float4 qv = *(const float4*)(Q + ((size_t)(b * T_ + q0 + row) * C_) + h * D_ + c4);
        *(float4*)&sQ[row * 64 + c4] = qv;
    }
    if (tid < 32) { sM[tid] = -1e30f; sL[tid] = 0.f; }

    float o[4][4];
#pragma unroll
    for (int i = 0; i < 4; i++)
#pragma unroll
        for (int j = 0; j < 4; j++) o[i][j] = 0.f;

    const float scale = 0.125f;

    for (int k0 = 0; k0 < T_; k0 += 64) {
        __syncthreads();
        for (int e = tid; e < 64 * 16; e += 128) {
            int row = e >> 4, c4 = (e & 15) << 2;
            size_t gof = ((size_t)(b * T_ + k0 + row) * C_) + h * D_ + c4;
            float4 kv = *(const float4*)(Kx + gof);
            sK[row * 65 + c4 + 0] = kv.x;
            sK[row * 65 + c4 + 1] = kv.y;
            sK[row * 65 + c4 + 2] = kv.z;
            sK[row * 65 + c4 + 3] = kv.w;
            float4 vv = *(const float4*)(Vx + gof);
            sV[row * 65 + c4 + 0] = vv.x;
            sV[row * 65 + c4 + 1] = vv.y;
            sV[row * 65 + c4 + 2] = vv.z;
            sV[row * 65 + c4 + 3] = vv.w;
        }
        __syncthreads();

        float s[4][4];
#pragma unroll
        for (int i = 0; i < 4; i++)
#pragma unroll
            for (int j = 0; j < 4; j++) s[i][j] = 0.f;
#pragma unroll 4
        for (int d = 0; d < 64; d++) {
            float qv[4], kv[4];
#pragma unroll
            for (int i = 0; i < 4; i++) qv[i] = sQ[(4 * ty + i) * 64 + d];
#pragma unroll
            for (int j = 0; j < 4; j++) kv[j] = sK[(4 * tx + j) * 65 + d];
#pragma unroll
            for (int i = 0; i < 4; i++)
#pragma unroll
                for (int j = 0; j < 4; j++) s[i][j] = fmaf(qv[i], kv[j], s[i][j]);
        }
        bool mok[4];
#pragma unroll
        for (int j = 0; j < 4; j++) mok[j] = mask[b * T_ + k0 + 4 * tx + j] != 0;
#pragma unroll
        for (int i = 0; i < 4; i++)
#pragma unroll
            for (int j = 0; j < 4; j++)
                sP[(4 * ty + i) * 65 + 4 * tx + j] = mok[j] ? s[i][j] * scale : -1e30f;
        __syncthreads();

        {
            int r = tid >> 2, sub = tid & 3;
            float mloc = -1e30f;
#pragma unroll
            for (int k = 0; k < 16; k++) mloc = fmaxf(mloc, sP[r * 65 + sub * 16 + k]);
            mloc = fmaxf(mloc, __shfl_xor_sync(~0u, mloc, 1));
            mloc = fmaxf(mloc, __shfl_xor_sync(~0u, mloc, 2));
            float mold = sM[r];
            float mnew = fmaxf(mold, mloc);
            float ssum = 0.f;
#pragma unroll
            for (int k = 0; k < 16; k++) {
                int idx = r * 65 + sub * 16 + k;
                float p = __expf(sP[idx] - mnew);
                sP[idx] = p;
                ssum += p;
            }
            ssum += __shfl_xor_sync(~0u, ssum, 1);
            ssum += __shfl_xor_sync(~0u, ssum, 2);
            if (sub == 0) {
                sF[r] = __expf(mold - mnew);
                sL[r] = sL[r] * sF[r] + ssum;
                sM[r] = mnew;
            }
        }
        __syncthreads();

        float fr[4];
#pragma unroll
        for (int i = 0; i < 4; i++) fr[i] = sF[4 * ty + i];
#pragma unroll
        for (int i = 0; i < 4; i++)
#pragma unroll
            for (int j = 0; j < 4; j++) o[i][j] *= fr[i];
#pragma unroll 4
        for (int c = 0; c < 64; c++) {
            float pv[4], vv[4];
#pragma unroll
            for (int i = 0; i < 4; i++) pv[i] = sP[(4 * ty + i) * 65 + c];
#pragma unroll
            for (int j = 0; j < 4; j++) vv[j] = sV[c * 65 + 4 * tx + j];
#pragma unroll
            for (int i = 0; i < 4; i++)
#pragma unroll
                for (int j = 0; j < 4; j++) o[i][j] = fmaf(pv[i], vv[j], o[i][j]);
        }
    }

#pragma unroll
    for (int i = 0; i < 4; i++) {
        int row = q0 + 4 * ty + i;
        float inv = 1.0f / sL[4 * ty + i];
        float4 ov;
        ov.x = o[i][0] * inv; ov.y = o[i][1] * inv;
        ov.z = o[i][2] * inv; ov.w = o[i][3] * inv;
        *(float4*)(Out + ((size_t)(b * T_ + row) * C_) + h * D_ + 4 * tx) = ov;
    }
}

// ---------------- host launcher ----------------
extern "C" void kernel_launch(void* const* d_in, const int* in_sizes, int n_in,
                              void* d_out, int out_size)
{
    const float* x    = (const float*)d_in[0];
    const int*   mask = (const int*)  d_in[1];
    const float* ln1w = (const float*)d_in[2];
    const float* ln1b = (const float*)d_in[3];
    const float* ln2w = (const float*)d_in[4];
    const float* ln2b = (const float*)d_in[5];
    const float* qw   = (const float*)d_in[6];
    const float* qb   = (const float*)d_in[7];
    const float* kw   = (const float*)d_in[8];
    const float* kb   = (const float*)d_in[9];
    const float* vw   = (const float*)d_in[10];
    const float* vb   = (const float*)d_in[11];
    const float* ow   = (const float*)d_in[12];
    const float* ob   = (const float*)d_in[13];
    const float* f1w  = (const float*)d_in[14];
    const float* f1b  = (const float*)d_in[15];
    const float* f2w  = (const float*)d_in[16];
    const float* f2b  = (const float*)d_in[17];
    const float* gm1  = (const float*)d_in[18];
    const float* gm2  = (const float*)d_in[19];
    float* out = (float*)d_out;

    float *b_h, *b_q, *b_k, *b_v, *b_att, *b_x1, *b_h2, *b_f1;
    cudaGetSymbolAddress((void**)&b_h,   g_h);
    cudaGetSymbolAddress((void**)&b_q,   g_q);
    cudaGetSymbolAddress((void**)&b_k,   g_k);
    cudaGetSymbolAddress((void**)&b_v,   g_v);
    cudaGetSymbolAddress((void**)&b_att, g_att);
    cudaGetSymbolAddress((void**)&b_x1,  g_x1);
    cudaGetSymbolAddress((void**)&b_h2,  g_h2);
    cudaGetSymbolAddress((void**)&b_f1,  g_f1);

    cudaFuncSetAttribute(attn_kernel,
                         cudaFuncAttributeMaxDynamicSharedMemorySize,
                         ATTN_SMEM_BYTES);

    dim3 gridC(C_ / 128, NTOK / 128);
    dim3 gridF(DFF / 128, NTOK / 128);

    ln_kernel<<<NTOK, 256>>>(x, ln1w, ln1b, b_h);
    bgemm_kernel<0><<<gridC, 256>>>(b_h, qw, qb, nullptr, nullptr, b_q, NTOK, C_, C_);
    bgemm_kernel<0><<<gridC, 256>>>(b_h, kw, kb, nullptr, nullptr, b_k, NTOK, C_, C_);
    bgemm_kernel<0><<<gridC, 256>>>(b_h, vw, vb, nullptr, nullptr, b_v, NTOK, C_, C_);
    attn_kernel<<<dim3(T_ / 32, H_, B_), 128, ATTN_SMEM_BYTES>>>(b_q, b_k, b_v, mask, b_att);
    bgemm_kernel<1><<<gridC, 256>>>(b_att, ow, ob, x, gm1, b_x1, NTOK, C_, C_);
    ln_kernel<<<NTOK, 256>>>(b_x1, ln2w, ln2b, b_h2);
    bgemm_kernel<2><<<gridF, 256>>>(b_h2, f1w, f1b, nullptr, nullptr, b_f1, NTOK, DFF, C_);
    bgemm_kernel<1><<<gridC, 256>>>(b_f1, f2w, f2b, b_x1, gm2, out, NTOK, C_, DFF);
}

// round 4
// speedup vs baseline: 6.2935x; 3.2955x over previous
#include <cuda_runtime.h>
#include <cuda_bf16.h>
#include <cstdint>
#include <math.h>

typedef unsigned int u32;

#define B_   2
#define T_   2048
#define C_   1024
#define H_   16
#define D_   64
#define NTOK (B_*T_)
#define DFF  4096
#define C3   (3*C_)

// ---------------- scratch (no allocation allowed) ----------------
__device__ __nv_bfloat16 g_hb  [NTOK*C_];
__device__ __nv_bfloat16 g_h2b [NTOK*C_];
__device__ __nv_bfloat16 g_qkv [NTOK*C3];
__device__ __nv_bfloat16 g_attb[NTOK*C_];
__device__ __nv_bfloat16 g_f1b [(size_t)NTOK*DFF];
__device__ float         g_x1  [NTOK*C_];
__device__ __nv_bfloat16 g_wqkv[C_*C3];
__device__ __nv_bfloat16 g_wo  [C_*C_];
__device__ __nv_bfloat16 g_wf1 [C_*DFF];
__device__ __nv_bfloat16 g_wf2 [DFF*C_];
__device__ float         g_bqkv[C3];

// ---------------- small helpers ----------------
__device__ __forceinline__ u32 pack_bf16(float x, float y) {
    __nv_bfloat162 t = __floats2bfloat162_rn(x, y);
    u32 r; memcpy(&r, &t, 4); return r;
}
__device__ __forceinline__ void cp16(u32 sdst, const void* gsrc) {
    asm volatile("cp.async.cg.shared.global [%0], [%1], 16;" :: "r"(sdst), "l"(gsrc));
}
__device__ __forceinline__ void cp_commit() { asm volatile("cp.async.commit_group;"); }
__device__ __forceinline__ void ldsm_x4(u32& r0, u32& r1, u32& r2, u32& r3, u32 addr) {
    asm volatile("ldmatrix.sync.aligned.m8n8.x4.shared.b16 {%0,%1,%2,%3},[%4];"
                 : "=r"(r0), "=r"(r1), "=r"(r2), "=r"(r3) : "r"(addr));
}
__device__ __forceinline__ void ldsm_x4_t(u32& r0, u32& r1, u32& r2, u32& r3, u32 addr) {
    asm volatile("ldmatrix.sync.aligned.m8n8.x4.trans.shared.b16 {%0,%1,%2,%3},[%4];"
                 : "=r"(r0), "=r"(r1), "=r"(r2), "=r"(r3) : "r"(addr));
}
__device__ __forceinline__ void mma_bf16(float* c, const u32* a, u32 b0, u32 b1) {
    asm volatile("mma.sync.aligned.m16n8k16.row.col.f32.bf16.bf16.f32 "
                 "{%0,%1,%2,%3},{%4,%5,%6,%7},{%8,%9},{%0,%1,%2,%3};"
                 : "+f"(c[0]), "+f"(c[1]), "+f"(c[2]), "+f"(c[3])
                 : "r"(a[0]), "r"(a[1]), "r"(a[2]), "r"(a[3]), "r"(b0), "r"(b1));
}
// FFMA-only exp (no MUFU). x <= ~0 expected; rel err ~2e-6.
__device__ __forceinline__ float fexp(float x) {
    x = fmaxf(x, -80.0f);
    float y = x * 1.4426950408889634f;
    float k = rintf(y);
    float t = (y - k) * 0.6931471805599453f;
    float p = fmaf(t, fmaf(t, fmaf(t, fmaf(t, fmaf(t, 8.3333333e-3f, 4.1666667e-2f),
                 0.16666667f), 0.5f), 1.0f), 1.0f);
    int ki = (int)k;
    return __int_as_float(__float_as_int(p) + (ki << 23));
}

// ---------------- weight conversion ----------------
__global__ void cvt_qkv_kernel(const float* __restrict__ qw, const float* __restrict__ kw,
                               const float* __restrict__ vw, const float* __restrict__ qb,
                               const float* __restrict__ kb, const float* __restrict__ vb)
{
    int gtid = blockIdx.x * blockDim.x + threadIdx.x;
    int stride = gridDim.x * blockDim.x;
    for (int i = gtid; i < C_*C_/4; i += stride) {
        int c = i / (C_/4), j = (i % (C_/4)) * 4;
        float4 q4 = *(const float4*)(qw + (size_t)c*C_ + j);
        float4 k4 = *(const float4*)(kw + (size_t)c*C_ + j);
        float4 v4 = *(const float4*)(vw + (size_t)c*C_ + j);
        uint2 qo = make_uint2(pack_bf16(q4.x,q4.y), pack_bf16(q4.z,q4.w));
        uint2 ko = make_uint2(pack_bf16(k4.x,k4.y), pack_bf16(k4.z,k4.w));
        uint2 vo = make_uint2(pack_bf16(v4.x,v4.y), pack_bf16(v4.z,v4.w));
        *(uint2*)(g_wqkv + (size_t)c*C3 + j)        = qo;
        *(uint2*)(g_wqkv + (size_t)c*C3 + C_ + j)   = ko;
        *(uint2*)(g_wqkv + (size_t)c*C3 + 2*C_ + j) = vo;
    }
    if (gtid < C_) {
        g_bqkv[gtid]        = qb[gtid];
        g_bqkv[C_ + gtid]   = kb[gtid];
        g_bqkv[2*C_ + gtid] = vb[gtid];
    }
}
__global__ void cvt_kernel(const float* __restrict__ src, __nv_bfloat16* __restrict__ dst, int n4)
{
    int gtid = blockIdx.x * blockDim.x + threadIdx.x;
    int stride = gridDim.x * blockDim.x;
    for (int i = gtid; i < n4; i += stride) {
        float4 s = *(const float4*)(src + (size_t)i*4);
        *(uint2*)(dst + (size_t)i*4) = make_uint2(pack_bf16(s.x,s.y), pack_bf16(s.z,s.w));
    }
}

// ---------------- LayerNorm: fp32 in -> bf16 out ----------------
__global__ void __launch_bounds__(256) ln_kernel(const float* __restrict__ x,
                                                 const float* __restrict__ w,
                                                 const float* __restrict__ b,
                                                 __nv_bfloat16* __restrict__ y)
{
    __shared__ float red[8];
    int row = blockIdx.x, tid = threadIdx.x;
    const float* xr = x + (size_t)row * C_;
    float4 v = *(const float4*)(xr + 4*tid);

    float s = v.x + v.y + v.z + v.w;
#pragma unroll
    for (int o = 16; o > 0; o >>= 1) s += __shfl_xor_sync(~0u, s, o);
    if ((tid & 31) == 0) red[tid >> 5] = s;
    __syncthreads();
    if (tid < 32) {
        float t = (tid < 8) ? red[tid] : 0.f;
#pragma unroll
        for (int o = 4; o > 0; o >>= 1) t += __shfl_xor_sync(~0u, t, o);
        if (tid == 0) red[0] = t;
    }
    __syncthreads();
    float mu = red[0] * (1.0f / C_);
    __syncthreads();

    float dx = v.x-mu, dy = v.y-mu, dz = v.z-mu, dw = v.w-mu;
    float sq = dx*dx + dy*dy + dz*dz + dw*dw;
#pragma unroll
    for (int o = 16; o > 0; o >>= 1) sq += __shfl_xor_sync(~0u, sq, o);
    if ((tid & 31) == 0) red[tid >> 5] = sq;
    __syncthreads();
    if (tid < 32) {
        float t = (tid < 8) ? red[tid] : 0.f;
#pragma unroll
        for (int o = 4; o > 0; o >>= 1) t += __shfl_xor_sync(~0u, t, o);
        if (tid == 0) red[0] = t;
    }
    __syncthreads();
    float rs = rsqrtf(red[0] * (1.0f / C_) + 1e-5f);
    float4 w4 = *(const float4*)(w + 4*tid);
    float4 b4 = *(const float4*)(b + 4*tid);
    float o0 = dx*rs*w4.x + b4.x, o1 = dy*rs*w4.y + b4.y;
    float o2 = dz*rs*w4.z + b4.z, o3 = dw*rs*w4.w + b4.w;
    *(uint2*)(y + (size_t)row*C_ + 4*tid) = make_uint2(pack_bf16(o0,o1), pack_bf16(o2,o3));
}

// ---------------- GEMM 128x128x32, bf16 in, cp.async, MMA ----------------
// MODE 0: out = acc + bias              (OBF: bf16 out)
// MODE 1: out = resid + gamma*(acc+bias) (fp32 out)
// MODE 2: out = gelu(acc + bias)         (OBF: bf16 out)
#define SA_STRIDE 20
#define SB_STRIDE 68
#define SA_U32   (128*SA_STRIDE)
#define SB_U32   (32*SB_STRIDE)
#define SA_BYTES (SA_U32*4)
#define SB_BYTES (SB_U32*4)

template<int MODE, int OBF>
__global__ void __launch_bounds__(256) bgemm_kernel(
    const __nv_bfloat16* __restrict__ A, const __nv_bfloat16* __restrict__ Bw,
    const float* __restrict__ bias,
    const float* __restrict__ resid, const float* __restrict__ gamma,
    void* __restrict__ CoutV, int M, int N, int K)
{
    __shared__ u32 sA[2][SA_U32];
    __shared__ u32 sB[2][SB_U32];

    const int tid  = threadIdx.x;
    const int lane = tid & 31, warp = tid >> 5;
    const int warp_m = warp >> 2, warp_n = warp & 3;
    const int m_blk = blockIdx.y << 7, n_blk = blockIdx.x << 7;

    // cp.async assignments
    const int ar = tid >> 2, ac = tid & 3;       // A rows 0..63 (+64), col16 0..3
    const int br = tid >> 4, bc = tid & 15;      // B rows 0..15 (+16), col16 0..15
    const __nv_bfloat16* Ag = A  + (size_t)(m_blk + ar) * K + ac*8;
    const __nv_bfloat16* Bg = Bw + (size_t)br * N + n_blk + bc*8;
    u32 sAbase = (u32)__cvta_generic_to_shared(&sA[0][0]);
    u32 sBbase = (u32)__cvta_generic_to_shared(&sB[0][0]);
    const u32 dA0 = sAbase + ar*80 + ac*16;
    const u32 dB0 = sBbase + br*272 + bc*16;

    // ldmatrix base addresses
    const int g  = lane >> 3;
    const int r8 = lane & 7;
    u32 aAddr0 = sAbase + (u32)(warp_m*64 + r8 + (g&1)*8) * 80 + (u32)((g>>1)*8) * 2;
    u32 bAddr0 = sBbase + (u32)(r8 + (g&1)*8) * 272 + (u32)(warp_n*32 + (g>>1)*8) * 2;

    float acc[4][4][4];
#pragma unroll
    for (int mt = 0; mt < 4; mt++)
#pragma unroll
        for (int nt = 0; nt < 4; nt++)
#pragma unroll
            for (int i = 0; i < 4; i++) acc[mt][nt][i] = 0.f;

    const int nk = K >> 5;
    // prologue: tile 0
    {
        cp16(dA0,          Ag);
        cp16(dA0 + 64*80,  Ag + (size_t)64*K);
        cp16(dB0,          Bg);
        cp16(dB0 + 16*272, Bg + (size_t)16*N);
        cp_commit();
    }

    for (int kt = 0; kt < nk; kt++) {
        const int cur = kt & 1;
        if (kt + 1 < nk) {
            const int nxt = cur ^ 1;
            const __nv_bfloat16* Agn = Ag + ((kt+1) << 5);
            const __nv_bfloat16* Bgn = Bg + (size_t)((kt+1) << 5) * N;
            cp16(dA0 + nxt*SA_BYTES,          Agn);
            cp16(dA0 + nxt*SA_BYTES + 64*80,  Agn + (size_t)64*K);
            cp16(dB0 + nxt*SB_BYTES,          Bgn);
            cp16(dB0 + nxt*SB_BYTES + 16*272, Bgn + (size_t)16*N);
            cp_commit();
            asm volatile("cp.async.wait_group 1;");
        } else {
            asm volatile("cp.async.wait_group 0;");
        }
        __syncthreads();

        const u32 aB = aAddr0 + cur * SA_BYTES;
        const u32 bB = bAddr0 + cur * SB_BYTES;
#pragma unroll
        for (int ks = 0; ks < 2; ks++) {
            u32 af[4][4];
#pragma unroll
            for (int mt = 0; mt < 4; mt++)
                ldsm_x4(af[mt][0], af[mt][1], af[mt][2], af[mt][3],
                        aB + (u32)(mt*16) * 80 + (u32)(ks*16)*2);
            u32 bf0[4], bf1[4];
            ldsm_x4_t(bf0[0], bf0[1], bf0[2], bf0[3], bB + (u32)(ks*16) * 272);
            ldsm_x4_t(bf1[0], bf1[1], bf1[2], bf1[3], bB + (u32)(ks*16) * 272 + 32);
#pragma unroll
            for (int mt = 0; mt < 4; mt++) {
                mma_bf16(acc[mt][0], af[mt], bf0[0], bf0[1]);
                mma_bf16(acc[mt][1], af[mt], bf0[2], bf0[3]);
                mma_bf16(acc[mt][2], af[mt], bf1[0], bf1[1]);
                mma_bf16(acc[mt][3], af[mt], bf1[2], bf1[3]);
            }
        }
        __syncthreads();
    }

    // ---- epilogue ----
    const int rr = lane >> 2, cc = (lane & 3) << 1;
    const int row0 = m_blk + warp_m * 64;
    const int col0 = n_blk + warp_n * 32;
#pragma unroll
    for (int mt = 0; mt < 4; mt++) {
#pragma unroll
        for (int nt = 0; nt < 4; nt++) {
            const int col = col0 + nt * 8 + cc;
            float2 b2 = *(const float2*)(bias + col);
            float2 g2 = make_float2(0.f, 0.f);
            if (MODE == 1) g2 = *(const float2*)(gamma + col);
#pragma unroll
            for (int half = 0; half < 2; half++) {
                const int row = row0 + mt * 16 + rr + half * 8;
                const size_t off = (size_t)row * N + col;
                float v0 = acc[mt][nt][half*2 + 0] + b2.x;
                float v1 = acc[mt][nt][half*2 + 1] + b2.y;
                if (MODE == 1) {
                    float2 rv = *(const float2*)(resid + off);
                    v0 = rv.x + g2.x * v0;
                    v1 = rv.y + g2.y * v1;
                } else if (MODE == 2) {
                    v0 = 0.5f * v0 * (1.0f + erff(v0 * 0.70710678118654752f));
                    v1 = 0.5f * v1 * (1.0f + erff(v1 * 0.70710678118654752f));
                }
                if (OBF) {
                    *(u32*)((__nv_bfloat16*)CoutV + off) = pack_bf16(v0, v1);
                } else {
                    *(float2*)((float*)CoutV + off) = make_float2(v0, v1);
                }
            }
        }
    }
}

// ---------------- Flash attention: bf16 MMA, fp32 softmax ----------------
// qkv: [NTOK][3072] bf16 (Q|K|V per row). One block: 64 queries x one head.
#define KV_ROWB  144                       // bytes per smem row (64 bf16 + 8 pad)
#define TILE_B   (64*KV_ROWB)              // 9216
#define SQ_OFF   0
#define SK_OFF   (TILE_B)
#define SV_OFF   (3*TILE_B)
#define SMSK_OFF (5*TILE_B)
#define ATTN_SMEM (5*TILE_B + 2*64*4)

__device__ __forceinline__ void attn_issue_kv(const __nv_bfloat16* __restrict__ qkv,
                                              u32 smb, int buf, int kt, int b, int h, int tid)
{
    const __nv_bfloat16* gK = qkv + ((size_t)(b*T_) + kt*64) * C3 + C_ + h*D_;
    const __nv_bfloat16* gV = gK + C_;
    u32 dK = smb + SK_OFF + buf*TILE_B;
    u32 dV = smb + SV_OFF + buf*TILE_B;
#pragma unroll
    for (int k = 0; k < 4; k++) {
        int c = tid + k*128;
        int row = c >> 3, col16 = c & 7;
        cp16(dK + row*KV_ROWB + col16*16, gK + (size_t)row*C3 + col16*8);
        cp16(dV + row*KV_ROWB + col16*16, gV + (size_t)row*C3 + col16*8);
    }
}

__global__ void __launch_bounds__(128) attn_kernel(
    const __nv_bfloat16* __restrict__ qkv, const int* __restrict__ mask,
    __nv_bfloat16* __restrict__ Out)
{
    extern __shared__ char attn_sm[];
    u32 smb = (u32)__cvta_generic_to_shared(attn_sm);
    float* sMask = (float*)(attn_sm + SMSK_OFF);

    const int tid = threadIdx.x;
    const int lane = tid & 31, warp = tid >> 5;
    const int b = blockIdx.z, h = blockIdx.y;
    const int q0 = blockIdx.x << 6;
    const int g = lane >> 3, r8 = lane & 7;
    const int qd = lane >> 2, qi = lane & 3;   // quad row / idx

    // issue Q + tile 0 (one group)
    {
        const __nv_bfloat16* gQ = qkv + ((size_t)(b*T_ + q0)) * C3 + h*D_;
#pragma unroll
        for (int k = 0; k < 4; k++) {
            int c = tid + k*128;
            int row = c >> 3, col16 = c & 7;
            cp16(smb + SQ_OFF + row*KV_ROWB + col16*16, gQ + (size_t)row*C3 + col16*8);
        }
        attn_issue_kv(qkv, smb, 0, 0, b, h, tid);
        if (tid < 64) sMask[tid] = mask[b*T_ + tid] ? 0.f : -1e30f;
        cp_commit();
    }

    float ofrag[8][4];
#pragma unroll
    for (int nt = 0; nt < 8; nt++)
#pragma unroll
        for (int i = 0; i < 4; i++) ofrag[nt][i] = 0.f;
    float mrow0 = -1e30f, mrow1 = -1e30f, lrow0 = 0.f, lrow1 = 0.f;
    u32 qf[4][4];

    const int NKT = T_ / 64;
    for (int kt = 0; kt < NKT; kt++) {
        const int cur = kt & 1;
        if (kt + 1 < NKT) {
            attn_issue_kv(qkv, smb, cur ^ 1, kt + 1, b, h, tid);
            if (tid < 64) sMask[(cur^1)*64 + tid] = mask[b*T_ + (kt+1)*64 + tid] ? 0.f : -1e30f;
            cp_commit();
            asm volatile("cp.async.wait_group 1;");
        } else {
            asm volatile("cp.async.wait_group 0;");
        }
        __syncthreads();

        if (kt == 0) {
#pragma unroll
            for (int ks = 0; ks < 4; ks++) {
                u32 addr = smb + SQ_OFF
                         + (u32)(warp*16 + r8 + (g&1)*8) * KV_ROWB
                         + (u32)(ks*16 + (g>>1)*8) * 2;
                ldsm_x4(qf[ks][0], qf[ks][1], qf[ks][2], qf[ks][3], addr);
            }
        }

        // ---- S = Q K^T ----
        float sfrag[8][4];
#pragma unroll
        for (int nt = 0; nt < 8; nt++)
#pragma unroll
            for (int i = 0; i < 4; i++) sfrag[nt][i] = 0.f;
        const u32 kBase = smb + SK_OFF + cur*TILE_B;
#pragma unroll
        for (int ks = 0; ks < 4; ks++) {
#pragma unroll
            for (int np = 0; np < 4; np++) {
                u32 k0, k1, k2, k3;
                u32 addr = kBase + (u32)(np*16 + (g>>1)*8 + r8) * KV_ROWB
                                 + (u32)(ks*16 + (g&1)*8) * 2;
                ldsm_x4(k0, k1, k2, k3, addr);
                mma_bf16(sfrag[2*np],   qf[ks], k0, k1);
                mma_bf16(sfrag[2*np+1], qf[ks], k2, k3);
            }
        }

        // ---- softmax (online, FFMA exp) ----
        const float* msk = sMask + cur*64;
        float mx0 = -1e30f, mx1 = -1e30f;
#pragma unroll
        for (int nt = 0; nt < 8; nt++) {
            float2 am = *(const float2*)(msk + nt*8 + 2*qi);
            sfrag[nt][0] = fmaf(sfrag[nt][0], 0.125f, am.x);
            sfrag[nt][1] = fmaf(sfrag[nt][1], 0.125f, am.y);
            sfrag[nt][2] = fmaf(sfrag[nt][2], 0.125f, am.x);
            sfrag[nt][3] = fmaf(sfrag[nt][3], 0.125f, am.y);
            mx0 = fmaxf(mx0, fmaxf(sfrag[nt][0], sfrag[nt][1]));
            mx1 = fmaxf(mx1, fmaxf(sfrag[nt][2], sfrag[nt][3]));
        }
        mx0 = fmaxf(mx0, __shfl_xor_sync(~0u, mx0, 1));
        mx0 = fmaxf(mx0, __shfl_xor_sync(~0u, mx0, 2));
        mx1 = fmaxf(mx1, __shfl_xor_sync(~0u, mx1, 1));
        mx1 = fmaxf(mx1, __shfl_xor_sync(~0u, mx1, 2));
        float mnew0 = fmaxf(mrow0, mx0), mnew1 = fmaxf(mrow1, mx1);
        float cor0 = fexp(mrow0 - mnew0), cor1 = fexp(mrow1 - mnew1);
        mrow0 = mnew0; mrow1 = mnew1;
        float ps0 = 0.f, ps1 = 0.f;
#pragma unroll
        for (int nt = 0; nt < 8; nt++) {
            sfrag[nt][0] = fexp(sfrag[nt][0] - mnew0);
            sfrag[nt][1] = fexp(sfrag[nt][1] - mnew0);
            sfrag[nt][2] = fexp(sfrag[nt][2] - mnew1);
            sfrag[nt][3] = fexp(sfrag[nt][3] - mnew1);
            ps0 += sfrag[nt][0] + sfrag[nt][1];
            ps1 += sfrag[nt][2] + sfrag[nt][3];
        }
        ps0 += __shfl_xor_sync(~0u, ps0, 1);
        ps0 += __shfl_xor_sync(~0u, ps0, 2);
        ps1 += __shfl_xor_sync(~0u, ps1, 1);
        ps1 += __shfl_xor_sync(~0u, ps1, 2);
        lrow0 = lrow0 * cor0 + ps0;
        lrow1 = lrow1 * cor1 + ps1;
#pragma unroll
        for (int nt = 0; nt < 8; nt++) {
            ofrag[nt][0] *= cor0; ofrag[nt][1] *= cor0;
            ofrag[nt][2] *= cor1; ofrag[nt][3] *= cor1;
        }

        // ---- O += P V ----
        const u32 vBase = smb + SV_OFF + cur*TILE_B;
#pragma unroll
        for (int kk = 0; kk < 4; kk++) {
            u32 a[4];
            a[0] = pack_bf16(sfrag[2*kk][0],   sfrag[2*kk][1]);
            a[1] = pack_bf16(sfrag[2*kk][2],   sfrag[2*kk][3]);
            a[2] = pack_bf16(sfrag[2*kk+1][0], sfrag[2*kk+1][1]);
            a[3] = pack_bf16(sfrag[2*kk+1][2], sfrag[2*kk+1][3]);
#pragma unroll
            for (int dp = 0; dp < 4; dp++) {
                u32 v0, v1, v2, v3;
                u32 addr = vBase + (u32)(kk*16 + r8 + (g&1)*8) * KV_ROWB
                                 + (u32)(dp*16 + (g>>1)*8) * 2;
                ldsm_x4_t(v0, v1, v2, v3, addr);
                mma_bf16(ofrag[2*dp],   a, v0, v1);
                mma_bf16(ofrag[2*dp+1], a, v2, v3);
            }
        }
        __syncthreads();
    }

    // ---- write output ----
    const float inv0 = 1.0f / lrow0, inv1 = 1.0f / lrow1;
    const int r0 = q0 + warp*16 + qd;
    const int r1 = r0 + 8;
    __nv_bfloat16* o0 = Out + (size_t)(b*T_ + r0) * C_ + h*D_ + 2*qi;
    __nv_bfloat16* o1 = Out + (size_t)(b*T_ + r1) * C_ + h*D_ + 2*qi;
#pragma unroll
    for (int nt = 0; nt < 8; nt++) {
        *(u32*)(o0 + nt*8) = pack_bf16(ofrag[nt][0]*inv0, ofrag[nt][1]*inv0);
        *(u32*)(o1 + nt*8) = pack_bf16(ofrag[nt][2]*inv1, ofrag[nt][3]*inv1);
    }
}

// ---------------- host launcher ----------------
extern "C" void kernel_launch(void* const* d_in, const int* in_sizes, int n_in,
                              void* d_out, int out_size)
{
    const float* x    = (const float*)d_in[0];
    const int*   mask = (const int*)  d_in[1];
    const float* ln1w = (const float*)d_in[2];
    const float* ln1b = (const float*)d_in[3];
    const float* ln2w = (const float*)d_in[4];
    const float* ln2b = (const float*)d_in[5];
    const float* qw   = (const float*)d_in[6];
    const float* qb   = (const float*)d_in[7];
    const float* kw   = (const float*)d_in[8];
    const float* kb   = (const float*)d_in[9];
    const float* vw   = (const float*)d_in[10];
    const float* vb   = (const float*)d_in[11];
    const float* ow   = (const float*)d_in[12];
    const float* ob   = (const float*)d_in[13];
    const float* f1w  = (const float*)d_in[14];
    const float* f1b  = (const float*)d_in[15];
    const float* f2w  = (const float*)d_in[16];
    const float* f2b  = (const float*)d_in[17];
    const float* gm1  = (const float*)d_in[18];
    const float* gm2  = (const float*)d_in[19];
    float* out = (float*)d_out;

    __nv_bfloat16 *b_h, *b_h2, *b_qkv, *b_att, *b_f1, *b_wqkv, *b_wo, *b_wf1, *b_wf2;
    float *b_x1, *b_bqkv;
    cudaGetSymbolAddress((void**)&b_h,    g_hb);
    cudaGetSymbolAddress((void**)&b_h2,   g_h2b);
    cudaGetSymbolAddress((void**)&b_qkv,  g_qkv);
    cudaGetSymbolAddress((void**)&b_att,  g_attb);
    cudaGetSymbolAddress((void**)&b_f1,   g_f1b);
    cudaGetSymbolAddress((void**)&b_x1,   g_x1);
    cudaGetSymbolAddress((void**)&b_wqkv, g_wqkv);
    cudaGetSymbolAddress((void**)&b_wo,   g_wo);
    cudaGetSymbolAddress((void**)&b_wf1,  g_wf1);
    cudaGetSymbolAddress((void**)&b_wf2,  g_wf2);
    cudaGetSymbolAddress((void**)&b_bqkv, g_bqkv);

    cudaFuncSetAttribute(attn_kernel,
                         cudaFuncAttributeMaxDynamicSharedMemorySize, ATTN_SMEM);

    // weight conversion
    cvt_qkv_kernel<<<1024, 256>>>(qw, kw, vw, qb, kb, vb);
    cvt_kernel<<<1024, 256>>>(ow,  b_wo,  C_*C_/4);
    cvt_kernel<<<2048, 256>>>(f1w, b_wf1, C_*DFF/4);
    cvt_kernel<<<2048, 256>>>(f2w, b_wf2, DFF*C_/4);

    dim3 gridQKV(C3 / 128, NTOK / 128);
    dim3 gridC  (C_ / 128, NTOK / 128);
    dim3 gridF  (DFF / 128, NTOK / 128);

    ln_kernel<<<NTOK, 256>>>(x, ln1w, ln1b, b_h);
    bgemm_kernel<0,1><<<gridQKV, 256>>>(b_h, b_wqkv, b_bqkv, nullptr, nullptr, b_qkv, NTOK, C3, C_);
    attn_kernel<<<dim3(T_/64, H_, B_), 128, ATTN_SMEM>>>(b_qkv, mask, b_att);
    bgemm_kernel<1,0><<<gridC, 256>>>(b_att, b_wo, ob, x, gm1, b_x1, NTOK, C_, C_);
    ln_kernel<<<NTOK, 256>>>(b_x1, ln2w, ln2b, b_h2);
    bgemm_kernel<2,1><<<gridF, 256>>>(b_h2, b_wf1, f1b, nullptr, nullptr, b_f1, NTOK, DFF, C_);
    bgemm_kernel<1,0><<<gridC, 256>>>(b_f1, b_wf2, f2b, b_x1, gm2, out, NTOK, C_, DFF);
}